// round 1
// baseline (speedup 1.0000x reference)
#include <cuda_runtime.h>
#include <math.h>

#define DD 128
#define HH 128
#define WW 128
#define HW (HH*WW)
#define NVOX (DD*HH*WW)
#define RAD 15
#define TAPS 31

// Scratch: pass1 out (8 labels x 3 h-orders), pass2 out (8 labels x 6 (d,h)-combos)
__device__ float g_s1[(size_t)24 * NVOX];   // ~201 MB
__device__ float g_s2[(size_t)48 * NVOX];   // ~402 MB
__device__ float g_w0[TAPS];
__device__ float g_w1[TAPS];
__device__ float g_w2[TAPS];

// ---------------------------------------------------------------------------
// Weight init: truncated gaussian, sigma=5, radius 15, normalized; plus
// first/second moment kernels delta*w, delta^2*w. Computed in double, cast.
// ---------------------------------------------------------------------------
__global__ void init_weights_kernel() {
    int t = threadIdx.x;
    if (t >= TAPS) return;
    double s = 0.0;
    for (int i = 0; i < TAPS; ++i) {
        double dd = (double)(i - RAD) / 5.0;
        s += exp(-0.5 * dd * dd);
    }
    double d  = (double)(t - RAD);
    double v  = exp(-0.5 * (d / 5.0) * (d / 5.0)) / s;
    g_w0[t] = (float)v;
    g_w1[t] = (float)(v * d);
    g_w2[t] = (float)(v * d * d);
}

// ---------------------------------------------------------------------------
// Pass 1: blur along H. For each voxel, per label, orders 0..2.
// seg (8MB) lives in L2; thread per voxel.
// ---------------------------------------------------------------------------
__global__ __launch_bounds__(128) void pass1_kernel(const int* __restrict__ seg) {
    __shared__ float sw0[TAPS], sw1[TAPS], sw2[TAPS];
    int w = threadIdx.x;
    int h = blockIdx.x;
    int d = blockIdx.y;
    if (w < TAPS) { sw0[w] = g_w0[w]; sw1[w] = g_w1[w]; sw2[w] = g_w2[w]; }
    __syncthreads();

    float a[8][3];
#pragma unroll
    for (int l = 0; l < 8; ++l) { a[l][0] = 0.f; a[l][1] = 0.f; a[l][2] = 0.f; }

    int lo = h - RAD; if (lo < 0) lo = 0;
    int hi = h + RAD; if (hi > HH - 1) hi = HH - 1;
    const int* p = seg + (size_t)d * HW + w;
    for (int hh = lo; hh <= hi; ++hh) {
        int s = __ldg(p + (size_t)hh * WW);
        int t = hh - h + RAD;
        float k0 = sw0[t], k1 = sw1[t], k2 = sw2[t];
#pragma unroll
        for (int l = 0; l < 8; ++l) {
            float m = (s == l + 1) ? 1.0f : 0.0f;
            a[l][0] = fmaf(m, k0, a[l][0]);
            a[l][1] = fmaf(m, k1, a[l][1]);
            a[l][2] = fmaf(m, k2, a[l][2]);
        }
    }
    size_t idx = (size_t)d * HW + (size_t)h * WW + w;
#pragma unroll
    for (int l = 0; l < 8; ++l)
#pragma unroll
        for (int c = 0; c < 3; ++c)
            g_s1[(size_t)(l * 3 + c) * NVOX + idx] = a[l][c];
}

// ---------------------------------------------------------------------------
// Pass 2: blur along D. smem tile: full 64-d half-column x 32 w, per label.
// 256 threads = 8 d-groups x 32 lanes; each thread produces 8 consecutive d
// outputs x 6 combos via a sliding 8-value register window (3 channels).
// Combos: 0:(d0,h0) 1:(d1,h0) 2:(d2,h0) 3:(d0,h1) 4:(d1,h1) 5:(d0,h2)
// ---------------------------------------------------------------------------
#define P2_DR 64
#define P2_PP (P2_DR + 2*RAD)   // 94

__global__ __launch_bounds__(256) void pass2_kernel() {
    __shared__ float sb[3][P2_PP][32];
    __shared__ float sw0[TAPS], sw1[TAPS], sw2[TAPS];
    int tid   = threadIdx.x;
    int wbase = blockIdx.x * 32;
    int h     = blockIdx.y;
    int dbase = blockIdx.z * P2_DR;
    if (tid < TAPS) { sw0[tid] = g_w0[tid]; sw1[tid] = g_w1[tid]; sw2[tid] = g_w2[tid]; }
    int wi   = tid & 31;
    int grp  = tid >> 5;
    int dloc = grp * 8;

    for (int l = 0; l < 8; ++l) {
        __syncthreads();
        // cooperative load of the 3 input channels (zero-padded in d)
        for (int c = 0; c < 3; ++c) {
            const float* src = g_s1 + (size_t)(l * 3 + c) * NVOX + (size_t)h * WW + wbase;
            for (int i = tid; i < P2_PP * 32; i += 256) {
                int pp = i >> 5, ww = i & 31;
                int dd = dbase + pp - RAD;
                float v = 0.0f;
                if (dd >= 0 && dd < DD) v = src[(size_t)dd * HW + ww];
                sb[c][pp][ww] = v;
            }
        }
        __syncthreads();

        float acc[8][6];
#pragma unroll
        for (int o = 0; o < 8; ++o)
#pragma unroll
            for (int cc = 0; cc < 6; ++cc) acc[o][cc] = 0.0f;

        float v0[8], v1[8], v2[8];
#pragma unroll
        for (int o = 0; o < 8; ++o) {
            v0[o] = sb[0][dloc + o][wi];
            v1[o] = sb[1][dloc + o][wi];
            v2[o] = sb[2][dloc + o][wi];
        }
#pragma unroll
        for (int t = 0; t < TAPS; ++t) {
            float k0 = sw0[t], k1 = sw1[t], k2 = sw2[t];
#pragma unroll
            for (int o = 0; o < 8; ++o) {
                acc[o][0] = fmaf(k0, v0[o], acc[o][0]);
                acc[o][1] = fmaf(k1, v0[o], acc[o][1]);
                acc[o][2] = fmaf(k2, v0[o], acc[o][2]);
                acc[o][3] = fmaf(k0, v1[o], acc[o][3]);
                acc[o][4] = fmaf(k1, v1[o], acc[o][4]);
                acc[o][5] = fmaf(k0, v2[o], acc[o][5]);
            }
            if (t < TAPS - 1) {
#pragma unroll
                for (int o = 0; o < 7; ++o) { v0[o] = v0[o+1]; v1[o] = v1[o+1]; v2[o] = v2[o+1]; }
                v0[7] = sb[0][dloc + t + 8][wi];
                v1[7] = sb[1][dloc + t + 8][wi];
                v2[7] = sb[2][dloc + t + 8][wi];
            }
        }
        size_t obase = (size_t)(dbase + dloc) * HW + (size_t)h * WW + wbase + wi;
#pragma unroll
        for (int o = 0; o < 8; ++o)
#pragma unroll
            for (int cc = 0; cc < 6; ++cc)
                g_s2[(size_t)(l * 6 + cc) * NVOX + obase + (size_t)o * HW] = acc[o][cc];
    }
}

// ---------------------------------------------------------------------------
// Pass 3: blur along W (contiguous) + descriptor assembly, own-label only.
// One block per (d,h) row: stage all 48 channels of the row in smem.
// ---------------------------------------------------------------------------
__global__ __launch_bounds__(128) void pass3_kernel(const int* __restrict__ seg,
                                                    float* __restrict__ out) {
    __shared__ float sm[48][WW];
    __shared__ float sw0[TAPS], sw1[TAPS], sw2[TAPS];
    int w = threadIdx.x;
    int h = blockIdx.x;
    int d = blockIdx.y;
    if (w < TAPS) { sw0[w] = g_w0[w]; sw1[w] = g_w1[w]; sw2[w] = g_w2[w]; }
    size_t base = (size_t)d * HW + (size_t)h * WW;
    for (int i = w; i < 48 * WW; i += 128) {
        int ch = i >> 7, ww = i & 127;
        sm[ch][ww] = g_s2[(size_t)ch * NVOX + base + ww];
    }
    __syncthreads();

    int L = seg[base + w];
    float r0=0,r1=0,r2=0,r3=0,r4=0,r5=0,r6=0,r7=0,r8=0,r9=0;
    if (L != 0) {
        int lb = (L - 1) * 6;
        float m0=0, m1d=0, m1h=0, m1w=0, mdd=0, mhh=0, mww=0, mdh=0, mhw=0, mdw=0;
        int t0 = (w < RAD) ? RAD - w : 0;
        int t1 = (w > WW - 1 - RAD) ? (WW - 1 - w) + RAD : TAPS - 1;
        for (int t = t0; t <= t1; ++t) {
            int pos = w + t - RAD;
            float k0 = sw0[t], k1 = sw1[t], k2 = sw2[t];
            float V0 = sm[lb + 0][pos];
            float V1 = sm[lb + 1][pos];
            float V2 = sm[lb + 2][pos];
            float V3 = sm[lb + 3][pos];
            float V4 = sm[lb + 4][pos];
            float V5 = sm[lb + 5][pos];
            m0  = fmaf(k0, V0, m0);
            m1d = fmaf(k0, V1, m1d);
            mdd = fmaf(k0, V2, mdd);
            m1h = fmaf(k0, V3, m1h);
            mdh = fmaf(k0, V4, mdh);
            mhh = fmaf(k0, V5, mhh);
            m1w = fmaf(k1, V0, m1w);
            mdw = fmaf(k1, V1, mdw);
            mhw = fmaf(k1, V3, mhw);
            mww = fmaf(k2, V0, mww);
        }
        float inv = 1.0f / m0;   // m0 >= w(0)^3 > 0 at a labeled voxel
        float od = m1d * inv, oh = m1h * inv, ow = m1w * inv;
        const float is2 = 1.0f / 25.0f;   // 1/sigma^2
        r0 = fmaf(od, 0.1f, 0.5f);        // (off/sigma)*0.5 + 0.5, sigma=5
        r1 = fmaf(oh, 0.1f, 0.5f);
        r2 = fmaf(ow, 0.1f, 0.5f);
        r3 = (mdd * inv - od * od) * is2;
        r4 = (mhh * inv - oh * oh) * is2;
        r5 = (mww * inv - ow * ow) * is2;
        r6 = (mdh * inv - od * oh) * is2;
        r7 = (mhw * inv - oh * ow) * is2;
        r8 = (mdw * inv - od * ow) * is2;
        r9 = m0;
    }
    float rr[10] = {r0,r1,r2,r3,r4,r5,r6,r7,r8,r9};
#pragma unroll
    for (int c = 0; c < 10; ++c) {
        float v = rr[c];
        v = fminf(fmaxf(v, 0.0f), 1.0f);
        out[(size_t)c * NVOX + base + w] = v;
    }
}

// ---------------------------------------------------------------------------
extern "C" void kernel_launch(void* const* d_in, const int* in_sizes, int n_in,
                              void* d_out, int out_size) {
    const int* seg = (const int*)d_in[0];
    // d_in[1] (coords) is a deterministic meshgrid == voxel indices; the
    // local-moment formulation makes it unnecessary.
    float* out = (float*)d_out;

    init_weights_kernel<<<1, 32>>>();
    pass1_kernel<<<dim3(HH, DD), 128>>>(seg);
    pass2_kernel<<<dim3(WW / 32, HH, DD / P2_DR), 256>>>();
    pass3_kernel<<<dim3(HH, DD), 128>>>(seg, out);
}